// round 12
// baseline (speedup 1.0000x reference)
#include <cuda_runtime.h>
#include <cstdint>
#include <cstddef>

#define NCH    64
#define OCH    64
#define CONVCH 4096
#define HH     56
#define WW     56
#define PLANE  (HH*WW)     // 3136
#define TROW   58          // full plane + 2 halo rows
#define TCOL   68          // row stride; fill rows 16B aligned; LDS.64 conflict-free
#define NREF   64          // refs per item: one a-half
#define NTHR   256
#define NACT   224         // 28 row-pairs * 8 overlapping strips
#define NJOB   (HH*14)     // 784 float4 fill jobs
#define OUTN   (8*OCH*PLANE)

typedef unsigned long long ull;

// Two channel-half partials per (b,o): scratch[ah][(b*64+o)*PLANE + px]
__device__ float g_scratch[2 * OUTN];   // 12.8 MB

__device__ __forceinline__ ull pk2(float lo, float hi) {
    ull r; asm("mov.b64 %0, {%1, %2};" : "=l"(r) : "f"(lo), "f"(hi)); return r;
}
__device__ __forceinline__ float2 up2(ull p) {
    float2 r; asm("mov.b64 {%0, %1}, %2;" : "=f"(r.x), "=f"(r.y) : "l"(p)); return r;
}
__device__ __forceinline__ ull f2fma(ull a, ull b, ull c) {
    ull d; asm("fma.rn.f32x2 %0, %1, %2, %3;" : "=l"(d) : "l"(a), "l"(b), "l"(c)); return d;
}

__device__ __forceinline__ void cp_async16(void* dst, const void* src) {
    unsigned d = (unsigned)__cvta_generic_to_shared(dst);
    asm volatile("cp.async.cg.shared.global [%0], [%1], 16;\n" :: "r"(d), "l"(src));
}
__device__ __forceinline__ void cp_commit() { asm volatile("cp.async.commit_group;\n" ::: "memory"); }
__device__ __forceinline__ void cp_wait0()  { asm volatile("cp.async.wait_group 0;\n" ::: "memory"); }

__global__ __launch_bounds__(NTHR, 3)
void prcn_kernel(const float* __restrict__ x,
                 const float* __restrict__ Wt,      // [4096,9]
                 const float* __restrict__ bias,    // [4096]
                 const void*  __restrict__ index_raw) // int32 or int64 [8192]
{
    __shared__ float tile[2][TROW][TCOL];   // 31552 B double buffer
    __shared__ ull   wsm2[NREF][10];        // (w,w) pairs: 9 weights + bias
    __shared__ int   cidx[NREF];

    const int tid = threadIdx.x;
    const int ah  = blockIdx.x & 1;          // a-half: refs [64*ah, 64*ah+64)
    const int o   = (blockIdx.x >> 1) & 63;
    const int b   = blockIdx.x >> 7;

    // --- index dtype detection: int32 (JAX x64 off) vs int64 ---
    const int* idx32 = (const int*)index_raw;
    const bool is64 = ((idx32[1] | idx32[3] | idx32[5] | idx32[7]) == 0);

    if (tid < NREF) {
        int j = o*128 + ah*64 + tid;
        int v = is64 ? (int)((const long long*)index_raw)[j] : idx32[j];
        cidx[tid] = v & (CONVCH - 1);
    }
    // Zero both buffers once. Fills rewrite rows 1..56, cols [4,59] every
    // channel; halo rows 0,57 and cols 0..3 / 60..67 stay zero forever.
    for (int j = tid; j < 2*TROW*TCOL; j += NTHR) ((float*)tile)[j] = 0.f;
    __syncthreads();
    for (int j = tid; j < NREF*10; j += NTHR) {
        int k = j / 10, l = j - k*10;
        int c = cidx[k];
        float v = (l < 9) ? Wt[c*9 + l] : bias[c];
        wsm2[k][l] = pk2(v, v);
    }
    __syncthreads();

    // Fill-job geometry: job j -> row rr=j/14, col cc=(j%14)*4. 784 = 3*256+16.
    int doff[4], soff[4];
    #pragma unroll
    for (int m = 0; m < 4; m++) {
        int j = tid + m*NTHR;
        int rr = j / 14, cc = (j - rr*14) * 4;
        doff[m] = (rr + 1)*TCOL + cc + 4;
        soff[m] = rr*WW + cc;
    }
    const bool job3 = (tid + 3*NTHR) < NJOB;   // only tid<16

    const int tr = tid >> 3;            // row-pair index 0..27 (tid < NACT)
    const int sx = tid & 7;             // strip index 0..7
    const int P  = (7*sx) & ~1;         // even first pixel; strips overlap by design
    const int ubase = P + 2;            // smem col of plane col P-2 (even, 8B aligned)

    // Prologue: fill(0)
    {
        const float* xp = x + (size_t)(b*NCH + (cidx[0] >> 6)) * PLANE;
        float* Tb = &tile[0][0][0];
        #pragma unroll
        for (int m = 0; m < 3; m++) cp_async16(Tb + doff[m], xp + soff[m]);
        if (job3) cp_async16(Tb + doff[3], xp + soff[3]);
        cp_commit();
    }

    // 8 px per row-pair: acc/mx scalar halves, S packed pairs
    float acc0[8], acc1[8], mx0[8], mx1[8];
    #pragma unroll
    for (int p = 0; p < 8; p++) { acc0[p] = 0.f; acc1[p] = 0.f; }

    for (int k = 0; k < NREF; k++) {
        cp_wait0();
        __syncthreads();

        if (k + 1 < NREF) {
            const float* xp = x + (size_t)(b*NCH + (cidx[k+1] >> 6)) * PLANE;
            float* Tb = &tile[(k+1) & 1][0][0];
            #pragma unroll
            for (int m = 0; m < 3; m++) cp_async16(Tb + doff[m], xp + soff[m]);
            if (job3) cp_async16(Tb + doff[3], xp + soff[3]);
            cp_commit();
        }

        if (tid < NACT) {
            const ull* wp = wsm2[k];
            const ull BP = wp[9];
            ull SA[4], SB[4];
            #pragma unroll
            for (int t = 0; t < 4; t++) { SA[t] = BP; SB[t] = BP; }

            // 4-row window; pair t = pixels (P+2t, P+2t+1).
            // u_i = plane col P-2+i; UP[m]=(u_2m,u_2m+1); O[t]=(UP[t].hi,UP[t+1].lo)
            // S[t] += w0*O[t] + w1*UP[t+1] + w2*O[t+1]
            #pragma unroll
            for (int ky = 0; ky < 4; ky++) {
                const ull* rp = (const ull*)&tile[k & 1][2*tr + ky][ubase];
                ull UP[6];
                #pragma unroll
                for (int m = 0; m < 6; m++) UP[m] = rp[m];
                ull O[5];
                #pragma unroll
                for (int t = 0; t < 5; t++) {
                    float2 a = up2(UP[t]), c = up2(UP[t+1]);
                    O[t] = pk2(a.y, c.x);
                }
                if (ky < 3) {
                    const ull w0 = wp[3*ky], w1 = wp[3*ky+1], w2 = wp[3*ky+2];
                    #pragma unroll
                    for (int t = 0; t < 4; t++)
                        SA[t] = f2fma(w0, O[t], f2fma(w1, UP[t+1], f2fma(w2, O[t+1], SA[t])));
                }
                if (ky > 0) {
                    const int kb = ky - 1;
                    const ull w0 = wp[3*kb], w1 = wp[3*kb+1], w2 = wp[3*kb+2];
                    #pragma unroll
                    for (int t = 0; t < 4; t++)
                        SB[t] = f2fma(w0, O[t], f2fma(w1, UP[t+1], f2fma(w2, O[t+1], SB[t])));
                }
            }

            if ((k & 7) == 0) {
                #pragma unroll
                for (int t = 0; t < 4; t++) {
                    float2 a = up2(SA[t]); mx0[2*t] = a.x; mx0[2*t+1] = a.y;
                    float2 c = up2(SB[t]); mx1[2*t] = c.x; mx1[2*t+1] = c.y;
                }
            } else {
                #pragma unroll
                for (int t = 0; t < 4; t++) {
                    float2 a = up2(SA[t]);
                    mx0[2*t]   = fmaxf(mx0[2*t],   a.x);
                    mx0[2*t+1] = fmaxf(mx0[2*t+1], a.y);
                    float2 c = up2(SB[t]);
                    mx1[2*t]   = fmaxf(mx1[2*t],   c.x);
                    mx1[2*t+1] = fmaxf(mx1[2*t+1], c.y);
                }
            }
            if ((k & 7) == 7) {
                #pragma unroll
                for (int p = 0; p < 8; p++) { acc0[p] += mx0[p]; acc1[p] += mx1[p]; }
            }
        }
    }

    if (tid < NACT) {
        // Overlapping strips write identical values -> deterministic.
        float* sp = g_scratch + (size_t)ah*OUTN
                  + ((size_t)(b*OCH + o)*HH + 2*tr)*WW + P;
        #pragma unroll
        for (int t = 0; t < 4; t++) {
            *(float2*)(sp + 2*t)      = make_float2(acc0[2*t], acc0[2*t+1]);
            *(float2*)(sp + WW + 2*t) = make_float2(acc1[2*t], acc1[2*t+1]);
        }
    }
}

__global__ __launch_bounds__(256)
void combine_kernel(float* __restrict__ out) {
    int j = blockIdx.x * 256 + threadIdx.x;     // float4 index
    if (j < OUTN/4) {
        const float4* s0 = (const float4*)g_scratch;
        const float4* s1 = (const float4*)(g_scratch + OUTN);
        float4 a = s0[j], c = s1[j];
        float4 r;
        r.x = (a.x + c.x) * 0.0625f;
        r.y = (a.y + c.y) * 0.0625f;
        r.z = (a.z + c.z) * 0.0625f;
        r.w = (a.w + c.w) * 0.0625f;
        ((float4*)out)[j] = r;
    }
}

extern "C" void kernel_launch(void* const* d_in, const int* in_sizes, int n_in,
                              void* d_out, int out_size) {
    const float* x    = (const float*)d_in[0];
    const float* Wt   = (const float*)d_in[1];
    const float* bias = (const float*)d_in[2];
    const void*  idx  = (const void*)d_in[3];
    float* out = (float*)d_out;
    prcn_kernel<<<8 * OCH * 2, NTHR>>>(x, Wt, bias, idx);
    combine_kernel<<<(OUTN/4 + 255) / 256, 256>>>(out);
}

// round 14
// speedup vs baseline: 1.3071x; 1.3071x over previous
#include <cuda_runtime.h>
#include <cstdint>
#include <cstddef>

#define NCH    64
#define OCH    64
#define CONVCH 4096
#define HH     56
#define WW     56
#define PLANE  (HH*WW)     // 3136
#define NPIX   14
#define TROW   58          // full plane + 2 halo rows
#define TCOL   68          // row stride; fill rows 16B aligned; LDS.64 conflict-free
#define NREF   64          // refs per item: one a-half (8 a-groups * 8 g)
#define NTHR   128
#define NACT   112         // 28 row-pairs * 4 col strips
#define NJOB   (HH*14)     // 784 float4 fill jobs
#define OUTN   (8*OCH*PLANE)

typedef unsigned long long ull;

// Two channel-half partials per (b,o): scratch[ah][(b*64+o)*PLANE + px]
__device__ float g_scratch[2 * OUTN];   // 12.8 MB

__device__ __forceinline__ ull pk2(float lo, float hi) {
    ull r; asm("mov.b64 %0, {%1, %2};" : "=l"(r) : "f"(lo), "f"(hi)); return r;
}
__device__ __forceinline__ float2 up2(ull p) {
    float2 r; asm("mov.b64 {%0, %1}, %2;" : "=f"(r.x), "=f"(r.y) : "l"(p)); return r;
}
__device__ __forceinline__ ull f2fma(ull a, ull b, ull c) {   // packed 2xFMA
    ull d; asm("fma.rn.f32x2 %0, %1, %2, %3;" : "=l"(d) : "l"(a), "l"(b), "l"(c)); return d;
}
__device__ __forceinline__ ull f2add(ull a, ull b) {          // packed 2xADD
    ull d; asm("add.rn.f32x2 %0, %1, %2;" : "=l"(d) : "l"(a), "l"(b)); return d;
}
// No max.f32x2 in PTX (verified: ptxas rejects). Half-wise scalar max; the
// mov.b64 pair split/join is register renaming in SASS, so cost = 2 FMNMX.
__device__ __forceinline__ ull f2max(ull a, ull b) {
    float2 x = up2(a), y = up2(b);
    return pk2(fmaxf(x.x, y.x), fmaxf(x.y, y.y));
}

__device__ __forceinline__ void cp_async16(void* dst, const void* src) {
    unsigned d = (unsigned)__cvta_generic_to_shared(dst);
    asm volatile("cp.async.cg.shared.global [%0], [%1], 16;\n" :: "r"(d), "l"(src));
}
__device__ __forceinline__ void cp_commit() { asm volatile("cp.async.commit_group;\n" ::: "memory"); }
__device__ __forceinline__ void cp_wait0()  { asm volatile("cp.async.wait_group 0;\n" ::: "memory"); }

__global__ __launch_bounds__(NTHR, 4)
void prcn_kernel(const float* __restrict__ x,
                 const float* __restrict__ Wt,      // [4096,9]
                 const float* __restrict__ bias,    // [4096]
                 const void*  __restrict__ index_raw) // int32 or int64 [8192]
{
    __shared__ float tile[2][TROW][TCOL];   // 31552 B double buffer
    __shared__ ull   wsm2[NREF][10];        // (w,w) pairs: 9 weights + bias
    __shared__ int   cidx[NREF];

    const int tid = threadIdx.x;
    const int ah  = blockIdx.x & 1;          // a-half: refs [64*ah, 64*ah+64)
    const int o   = (blockIdx.x >> 1) & 63;
    const int b   = blockIdx.x >> 7;

    // --- index dtype detection: int32 (JAX x64 off) vs int64 ---
    const int* idx32 = (const int*)index_raw;
    const bool is64 = ((idx32[1] | idx32[3] | idx32[5] | idx32[7]) == 0);

    if (tid < NREF) {
        int j = o*128 + ah*64 + tid;
        int v = is64 ? (int)((const long long*)index_raw)[j] : idx32[j];
        cidx[tid] = v & (CONVCH - 1);
    }
    // Zero both buffers once. Fills rewrite rows 1..56, cols [4,59] every
    // channel; halo rows 0,57 and cols 0..3 / 60..67 stay zero forever.
    for (int j = tid; j < 2*TROW*TCOL; j += NTHR) ((float*)tile)[j] = 0.f;
    __syncthreads();
    for (int j = tid; j < NREF*10; j += NTHR) {
        int k = j / 10, l = j - k*10;
        int c = cidx[k];
        float v = (l < 9) ? Wt[c*9 + l] : bias[c];
        wsm2[k][l] = pk2(v, v);              // pre-duplicated broadcast pair
    }
    __syncthreads();

    // Fill-job geometry: job j -> row rr=j/14, col cc=(j%14)*4.
    int doff[7], soff[7];
    #pragma unroll
    for (int m = 0; m < 7; m++) {
        int j = tid + m*NTHR;
        int rr = j / 14, cc = (j - rr*14) * 4;
        doff[m] = (rr + 1)*TCOL + cc + 4;
        soff[m] = rr*WW + cc;
    }
    const bool job6 = (tid + 6*NTHR) < NJOB;

    const int tr = tid >> 2;        // row-pair index 0..27 (tid < NACT)
    const int tx = tid & 3;
    const int ubase = 14*tx + 2;    // even smem col; u[i] = plane col 14tx-2+i

    // Prologue: fill(0)
    {
        const float* xp = x + (size_t)(b*NCH + (cidx[0] >> 6)) * PLANE;
        float* Tb = &tile[0][0][0];
        #pragma unroll
        for (int m = 0; m < 6; m++) cp_async16(Tb + doff[m], xp + soff[m]);
        if (job6) cp_async16(Tb + doff[6], xp + soff[6]);
        cp_commit();
    }

    // Packed reduction state: 7 pixel-pairs per output row
    ull AC0[7], AC1[7], MX0[7], MX1[7];
    #pragma unroll
    for (int j = 0; j < 7; j++) { AC0[j] = 0ULL; AC1[j] = 0ULL; }

    for (int k = 0; k < NREF; k++) {
        cp_wait0();
        __syncthreads();

        if (k + 1 < NREF) {
            const float* xp = x + (size_t)(b*NCH + (cidx[k+1] >> 6)) * PLANE;
            float* Tb = &tile[(k+1) & 1][0][0];
            #pragma unroll
            for (int m = 0; m < 6; m++) cp_async16(Tb + doff[m], xp + soff[m]);
            if (job6) cp_async16(Tb + doff[6], xp + soff[6]);
            cp_commit();
        }

        if (tid < NACT) {
            const ull* wp = wsm2[k];
            const ull BP = wp[9];            // packed bias broadcast
            ull SA[7], SB[7];
            #pragma unroll
            for (int j = 0; j < 7; j++) { SA[j] = BP; SB[j] = BP; }

            // 4-row window, pixel-pair packed f32x2 conv.
            // v[i] = u[i+1]; E_j=(hi UP[j], lo UP[j+1]); O_j=UP[j+1].
            #pragma unroll
            for (int ky = 0; ky < 4; ky++) {
                const ull* rp = (const ull*)&tile[k & 1][2*tr + ky][ubase];
                ull UP[9];
                #pragma unroll
                for (int m = 0; m < 9; m++) UP[m] = rp[m];
                ull E[8];
                #pragma unroll
                for (int j = 0; j < 8; j++) {
                    float2 a = up2(UP[j]), c = up2(UP[j+1]);
                    E[j] = pk2(a.y, c.x);
                }
                if (ky < 3) {
                    const ull w0 = wp[3*ky], w1 = wp[3*ky+1], w2 = wp[3*ky+2];
                    #pragma unroll
                    for (int j = 0; j < 7; j++)
                        SA[j] = f2fma(w0, E[j], f2fma(w1, UP[j+1], f2fma(w2, E[j+1], SA[j])));
                }
                if (ky > 0) {
                    const int kb = ky - 1;
                    const ull w0 = wp[3*kb], w1 = wp[3*kb+1], w2 = wp[3*kb+2];
                    #pragma unroll
                    for (int j = 0; j < 7; j++)
                        SB[j] = f2fma(w0, E[j], f2fma(w1, UP[j+1], f2fma(w2, E[j+1], SB[j])));
                }
            }

            // Max-over-g (half-wise FMNMX) / packed accumulate-over-a
            if ((k & 7) == 0) {
                #pragma unroll
                for (int j = 0; j < 7; j++) { MX0[j] = SA[j]; MX1[j] = SB[j]; }
            } else {
                #pragma unroll
                for (int j = 0; j < 7; j++) {
                    MX0[j] = f2max(MX0[j], SA[j]);
                    MX1[j] = f2max(MX1[j], SB[j]);
                }
            }
            if ((k & 7) == 7) {
                #pragma unroll
                for (int j = 0; j < 7; j++) {
                    AC0[j] = f2add(AC0[j], MX0[j]);
                    AC1[j] = f2add(AC1[j], MX1[j]);
                }
            }
        }
    }

    if (tid < NACT) {
        float* sp = g_scratch + (size_t)ah*OUTN
                  + ((size_t)(b*OCH + o)*HH + 2*tr)*WW + tx*NPIX;
        #pragma unroll
        for (int j = 0; j < 7; j++) {
            float2 a = up2(AC0[j]);
            *(float2*)(sp + 2*j) = a;
            float2 c = up2(AC1[j]);
            *(float2*)(sp + WW + 2*j) = c;
        }
    }
}

__global__ __launch_bounds__(256)
void combine_kernel(float* __restrict__ out) {
    int j = blockIdx.x * 256 + threadIdx.x;     // float4 index
    if (j < OUTN/4) {
        const float4* s0 = (const float4*)g_scratch;
        const float4* s1 = (const float4*)(g_scratch + OUTN);
        float4 a = s0[j], c = s1[j];
        float4 r;
        r.x = (a.x + c.x) * 0.0625f;
        r.y = (a.y + c.y) * 0.0625f;
        r.z = (a.z + c.z) * 0.0625f;
        r.w = (a.w + c.w) * 0.0625f;
        ((float4*)out)[j] = r;
    }
}

extern "C" void kernel_launch(void* const* d_in, const int* in_sizes, int n_in,
                              void* d_out, int out_size) {
    const float* x    = (const float*)d_in[0];
    const float* Wt   = (const float*)d_in[1];
    const float* bias = (const float*)d_in[2];
    const void*  idx  = (const void*)d_in[3];
    float* out = (float*)d_out;
    prcn_kernel<<<8 * OCH * 2, NTHR>>>(x, Wt, bias, idx);
    combine_kernel<<<(OUTN/4 + 255) / 256, 256>>>(out);
}

// round 16
// speedup vs baseline: 1.3256x; 1.0142x over previous
#include <cuda_runtime.h>
#include <cstdint>
#include <cstddef>

#define NCH    64
#define OCH    64
#define CONVCH 4096
#define HH     56
#define WW     56
#define PLANE  (HH*WW)     // 3136
#define NPIX   14
#define TROWH  30          // half plane (28 rows) + 2 halo rows
#define TCOL   68          // row stride; fill rows 16B aligned; LDS.64 conflict-free
#define NREF   64          // refs per item: one a-half (8 a-groups * 8 g)
#define NTHR   64          // 2 warps per block -> 8 independent blocks/SM
#define NACT   56          // 14 row-pairs * 4 col strips
#define NJOB   (TROWH*14)  // 420 float4 fill jobs per tile
#define OUTN   (8*OCH*PLANE)

typedef unsigned long long ull;

// Two channel-half partials per (b,o): scratch[ah][(b*64+o)*PLANE + px]
__device__ float g_scratch[2 * OUTN];   // 12.8 MB

__device__ __forceinline__ ull pk2(float lo, float hi) {
    ull r; asm("mov.b64 %0, {%1, %2};" : "=l"(r) : "f"(lo), "f"(hi)); return r;
}
__device__ __forceinline__ float2 up2(ull p) {
    float2 r; asm("mov.b64 {%0, %1}, %2;" : "=f"(r.x), "=f"(r.y) : "l"(p)); return r;
}
__device__ __forceinline__ ull f2fma(ull a, ull b, ull c) {   // packed 2xFMA
    ull d; asm("fma.rn.f32x2 %0, %1, %2, %3;" : "=l"(d) : "l"(a), "l"(b), "l"(c)); return d;
}
__device__ __forceinline__ ull f2add(ull a, ull b) {          // packed 2xADD
    ull d; asm("add.rn.f32x2 %0, %1, %2;" : "=l"(d) : "l"(a), "l"(b)); return d;
}
// No max.f32x2 in PTX (ptxas rejects). Half-wise scalar max (movs are renaming).
__device__ __forceinline__ ull f2max(ull a, ull b) {
    float2 x = up2(a), y = up2(b);
    return pk2(fmaxf(x.x, y.x), fmaxf(x.y, y.y));
}

__device__ __forceinline__ void cp_async16(void* dst, const void* src) {
    unsigned d = (unsigned)__cvta_generic_to_shared(dst);
    asm volatile("cp.async.cg.shared.global [%0], [%1], 16;\n" :: "r"(d), "l"(src));
}
__device__ __forceinline__ void cp_commit() { asm volatile("cp.async.commit_group;\n" ::: "memory"); }
__device__ __forceinline__ void cp_wait0()  { asm volatile("cp.async.wait_group 0;\n" ::: "memory"); }

__global__ __launch_bounds__(NTHR, 8)
void prcn_kernel(const float* __restrict__ x,
                 const float* __restrict__ Wt,      // [4096,9]
                 const float* __restrict__ bias,    // [4096]
                 const void*  __restrict__ index_raw) // int32 or int64 [8192]
{
    __shared__ float tile[2][TROWH][TCOL];  // 16320 B double buffer
    __shared__ ull   wsm2[NREF][10];        // (w,w) pairs: 9 weights + bias
    __shared__ int   cidx[NREF];

    const int tid = threadIdx.x;
    const int bi  = blockIdx.x;
    const int ah  = bi & 1;                 // a-half: refs [64*ah, 64*ah+64)
    const int hr  = (bi >> 1) & 1;          // row-half: output rows [28*hr, 28*hr+28)
    const int o   = (bi >> 2) & 63;
    const int b   = bi >> 8;

    // --- index dtype detection: int32 (JAX x64 off) vs int64 ---
    const int* idx32 = (const int*)index_raw;
    const bool is64 = ((idx32[1] | idx32[3] | idx32[5] | idx32[7]) == 0);

    if (tid < NREF) {
        int j = o*128 + ah*64 + tid;
        int v = is64 ? (int)((const long long*)index_raw)[j] : idx32[j];
        cidx[tid] = v & (CONVCH - 1);
    }
    // Zero both buffers once. Fills rewrite all rows with a valid plane row,
    // cols [4,59]; the one halo row (top for hr=0, bottom for hr=1) and cols
    // 0..3 / 60..67 stay zero forever.
    for (int j = tid; j < 2*TROWH*TCOL; j += NTHR) ((float*)tile)[j] = 0.f;
    __syncthreads();
    for (int j = tid; j < NREF*10; j += NTHR) {
        int k = j / 10, l = j - k*10;
        int c = cidx[k];
        float v = (l < 9) ? Wt[c*9 + l] : bias[c];
        wsm2[k][l] = pk2(v, v);             // pre-duplicated broadcast pair
    }
    __syncthreads();

    // Fill-job geometry: job j -> tile row rr=j/14 (plane row 28*hr-1+rr),
    // col cc=(j%14)*4. 420 jobs over 64 threads -> up to 7 each.
    int doff[7], soff[7];
    bool jok[7];
    #pragma unroll
    for (int m = 0; m < 7; m++) {
        int j = tid + m*NTHR;
        int rr = j / 14, cc = (j - rr*14) * 4;
        int pr = hr*28 - 1 + rr;
        jok[m]  = (j < NJOB) && (pr >= 0) && (pr < HH);
        doff[m] = rr*TCOL + cc + 4;
        soff[m] = pr*WW + cc;
    }

    const int tr = tid >> 2;        // row-pair index 0..13 (tid < NACT)
    const int tx = tid & 3;
    const int ubase = 14*tx + 2;    // even smem col; u[i] = plane col 14tx-2+i

    // Prologue: fill(0)
    {
        const float* xp = x + (size_t)(b*NCH + (cidx[0] >> 6)) * PLANE;
        float* Tb = &tile[0][0][0];
        #pragma unroll
        for (int m = 0; m < 7; m++)
            if (jok[m]) cp_async16(Tb + doff[m], xp + soff[m]);
        cp_commit();
    }

    // Packed reduction state: 7 pixel-pairs per output row
    ull AC0[7], AC1[7], MX0[7], MX1[7];
    #pragma unroll
    for (int j = 0; j < 7; j++) { AC0[j] = 0ULL; AC1[j] = 0ULL; }

    for (int k = 0; k < NREF; k++) {
        cp_wait0();
        __syncthreads();

        if (k + 1 < NREF) {
            const float* xp = x + (size_t)(b*NCH + (cidx[k+1] >> 6)) * PLANE;
            float* Tb = &tile[(k+1) & 1][0][0];
            #pragma unroll
            for (int m = 0; m < 7; m++)
                if (jok[m]) cp_async16(Tb + doff[m], xp + soff[m]);
            cp_commit();
        }

        if (tid < NACT) {
            const ull* wp = wsm2[k];
            const ull BP = wp[9];            // packed bias broadcast
            ull SA[7], SB[7];
            #pragma unroll
            for (int j = 0; j < 7; j++) { SA[j] = BP; SB[j] = BP; }

            // 4-row window (tile rows 2tr..2tr+3 = plane rows 28hr+2tr-1..+2).
            // Pixel-pair packed f32x2 conv: E_j=(hi UP[j], lo UP[j+1]).
            #pragma unroll
            for (int ky = 0; ky < 4; ky++) {
                const ull* rp = (const ull*)&tile[k & 1][2*tr + ky][ubase];
                ull UP[9];
                #pragma unroll
                for (int m = 0; m < 9; m++) UP[m] = rp[m];
                ull E[8];
                #pragma unroll
                for (int j = 0; j < 8; j++) {
                    float2 a = up2(UP[j]), c = up2(UP[j+1]);
                    E[j] = pk2(a.y, c.x);
                }
                if (ky < 3) {
                    const ull w0 = wp[3*ky], w1 = wp[3*ky+1], w2 = wp[3*ky+2];
                    #pragma unroll
                    for (int j = 0; j < 7; j++)
                        SA[j] = f2fma(w0, E[j], f2fma(w1, UP[j+1], f2fma(w2, E[j+1], SA[j])));
                }
                if (ky > 0) {
                    const int kb = ky - 1;
                    const ull w0 = wp[3*kb], w1 = wp[3*kb+1], w2 = wp[3*kb+2];
                    #pragma unroll
                    for (int j = 0; j < 7; j++)
                        SB[j] = f2fma(w0, E[j], f2fma(w1, UP[j+1], f2fma(w2, E[j+1], SB[j])));
                }
            }

            // Max-over-g (half-wise FMNMX) / packed accumulate-over-a
            if ((k & 7) == 0) {
                #pragma unroll
                for (int j = 0; j < 7; j++) { MX0[j] = SA[j]; MX1[j] = SB[j]; }
            } else {
                #pragma unroll
                for (int j = 0; j < 7; j++) {
                    MX0[j] = f2max(MX0[j], SA[j]);
                    MX1[j] = f2max(MX1[j], SB[j]);
                }
            }
            if ((k & 7) == 7) {
                #pragma unroll
                for (int j = 0; j < 7; j++) {
                    AC0[j] = f2add(AC0[j], MX0[j]);
                    AC1[j] = f2add(AC1[j], MX1[j]);
                }
            }
        }
    }

    if (tid < NACT) {
        float* sp = g_scratch + (size_t)ah*OUTN
                  + ((size_t)(b*OCH + o)*HH + hr*28 + 2*tr)*WW + tx*NPIX;
        #pragma unroll
        for (int j = 0; j < 7; j++) {
            float2 a = up2(AC0[j]);
            *(float2*)(sp + 2*j) = a;
            float2 c = up2(AC1[j]);
            *(float2*)(sp + WW + 2*j) = c;
        }
    }
}

__global__ __launch_bounds__(256)
void combine_kernel(float* __restrict__ out) {
    int j = blockIdx.x * 256 + threadIdx.x;     // float4 index
    if (j < OUTN/4) {
        const float4* s0 = (const float4*)g_scratch;
        const float4* s1 = (const float4*)(g_scratch + OUTN);
        float4 a = s0[j], c = s1[j];
        float4 r;
        r.x = (a.x + c.x) * 0.0625f;
        r.y = (a.y + c.y) * 0.0625f;
        r.z = (a.z + c.z) * 0.0625f;
        r.w = (a.w + c.w) * 0.0625f;
        ((float4*)out)[j] = r;
    }
}

extern "C" void kernel_launch(void* const* d_in, const int* in_sizes, int n_in,
                              void* d_out, int out_size) {
    const float* x    = (const float*)d_in[0];
    const float* Wt   = (const float*)d_in[1];
    const float* bias = (const float*)d_in[2];
    const void*  idx  = (const void*)d_in[3];
    float* out = (float*)d_out;
    prcn_kernel<<<8 * OCH * 2 * 2, NTHR>>>(x, Wt, bias, idx);
    combine_kernel<<<(OUTN/4 + 255) / 256, 256>>>(out);
}